// round 16
// baseline (speedup 1.0000x reference)
#include <cuda_runtime.h>
#include <math.h>
#include <stddef.h>

#define H 100
#define G 400            // 4*H
#define BATCH 512
#define TT 1024
#define FF 64
#define NTOK (BATCH * TT)        // 524288
#define RPB 4                    // batch rows per LSTM CTA
#define LSTM_CTAS (BATCH / RPB)  // 128
#define LSTM_THREADS 800         // (k-quarter, logical col-pair)
#define KQ 25                    // k per quarter
#define GEMM_ROWS 16
#define GEMM_THREADS 200
#define AS_STRIDE 24             // padded [k][row] stride (96B, 16B-aligned)

typedef unsigned long long u64;

// Scratch (static device allocation: no cudaMalloc allowed)
// g_xw padded by one timestep (G floats) so the lstm prefetch can over-read
// harmlessly on the final iteration (value unused).
__device__ float g_xw[(size_t)NTOK * G + G];   // 838.9 MB + pad
__device__ float g_h1[(size_t)NTOK * H];       // 209.7 MB
__device__ float g_h2last[BATCH * H];

// ---------------------------------------------------------------------------
// f32x2 packed helpers (sm_100+)
// ---------------------------------------------------------------------------
__device__ __forceinline__ u64 f2dup(float x)
{
    u64 r;
    asm("mov.b64 %0, {%1, %1};" : "=l"(r) : "f"(x));
    return r;
}
__device__ __forceinline__ u64 f2pack(float lo, float hi)
{
    u64 r;
    asm("mov.b64 %0, {%1, %2};" : "=l"(r) : "f"(lo), "f"(hi));
    return r;
}
__device__ __forceinline__ void fma2(u64& d, u64 a, u64 b)
{
    asm("fma.rn.f32x2 %0, %1, %2, %0;" : "+l"(d) : "l"(a), "l"(b));
}
__device__ __forceinline__ u64 add2(u64 a, u64 b)
{
    u64 r;
    asm("add.rn.f32x2 %0, %1, %2;" : "=l"(r) : "l"(a), "l"(b));
    return r;
}
__device__ __forceinline__ float2 unpk(u64 v)
{
    float2 r;
    asm("mov.b64 {%0, %1}, %2;" : "=f"(r.x), "=f"(r.y) : "l"(v));
    return r;
}

// ---------------------------------------------------------------------------
// Fast transcendentals: MUFU ex2/rcp (abs err ~1e-6, far under 1e-3 budget)
// ---------------------------------------------------------------------------
#define LOG2E 1.4426950408889634f
__device__ __forceinline__ float ex2a(float x)
{
    float r;
    asm("ex2.approx.f32 %0, %1;" : "=f"(r) : "f"(x));
    return r;
}
__device__ __forceinline__ float rcpa(float x)
{
    float r;
    asm("rcp.approx.f32 %0, %1;" : "=f"(r) : "f"(x));
    return r;
}
__device__ __forceinline__ float fast_sig(float x)
{
    return rcpa(1.f + ex2a(-x * LOG2E));             // 1/(1+e^-x)
}
__device__ __forceinline__ float fast_tanh(float x)
{
    // tanh(x) = 2*sigmoid(2x) - 1
    return fmaf(2.f, rcpa(1.f + ex2a(-2.f * LOG2E * x)), -1.f);
}

// ---------------------------------------------------------------------------
// Pre-activation GEMM v3 (the PROVEN 4784us version, unroll x1):
// out[N,400] = A[N,K] @ Wm[K,400] + bias. 200 threads = col-pairs, ROWS=16,
// acc lanes = row pairs, broadcast A quads, 4 CTAs/SM.
// ---------------------------------------------------------------------------
template <int K>
__global__ void __launch_bounds__(GEMM_THREADS, 4)
pregemm_kernel(const float* __restrict__ A, const float* __restrict__ Wm,
               const float* __restrict__ bias, float* __restrict__ out)
{
    __shared__ __align__(16) float A_s[K * AS_STRIDE];
    const int tid = threadIdx.x;
    const size_t row0 = (size_t)blockIdx.x * GEMM_ROWS;

    const float* Atile = A + row0 * K;
    for (int i = tid; i < GEMM_ROWS * K; i += GEMM_THREADS) {
        const int r = i / K;
        const int k = i % K;
        A_s[k * AS_STRIDE + r] = Atile[i];
    }
    __syncthreads();

    const int c0 = 2 * tid;                 // this thread's column pair
    u64 acc[16];                            // [4 quads][2 rowpairs][2 cols]
#pragma unroll
    for (int i = 0; i < 16; ++i) acc[i] = 0ull;

    float2 w = *(const float2*)&Wm[c0];     // k=0 prefetch
    for (int k = 0; k < K; ++k) {
        float2 wn;
        if (k + 1 < K) wn = *(const float2*)&Wm[(k + 1) * G + c0];
        const u64 w0 = f2dup(w.x);
        const u64 w1 = f2dup(w.y);
        const float* ak = &A_s[k * AS_STRIDE];
#pragma unroll
        for (int qd = 0; qd < 4; ++qd) {
            const ulonglong2 a = *(const ulonglong2*)(ak + qd * 4); // rows 4qd..4qd+3
            fma2(acc[qd * 4 + 0], a.x, w0);
            fma2(acc[qd * 4 + 1], a.x, w1);
            fma2(acc[qd * 4 + 2], a.y, w0);
            fma2(acc[qd * 4 + 3], a.y, w1);
        }
        if (k + 1 < K) w = wn;
    }

    const float2 bc = *(const float2*)&bias[c0];
#pragma unroll
    for (int qd = 0; qd < 4; ++qd) {
#pragma unroll
        for (int hp = 0; hp < 2; ++hp) {
            const float2 v0 = unpk(acc[qd * 4 + hp * 2 + 0]);
            const float2 v1 = unpk(acc[qd * 4 + hp * 2 + 1]);
            const int ra = 4 * qd + 2 * hp;
            *(float2*)&out[(row0 + ra) * G + c0]     = make_float2(v0.x + bc.x, v1.x + bc.y);
            *(float2*)&out[(row0 + ra + 1) * G + c0] = make_float2(v0.y + bc.x, v1.y + bc.y);
        }
    }
}

// ---------------------------------------------------------------------------
// Persistent LSTM layer: PROVEN 4784us structure. Two micro-edits only:
// (1) unconditional zpre prefetch (g_xw padded; final over-read unused),
// (2) running h_all pointer instead of per-step 64-bit address mul.
// ---------------------------------------------------------------------------
template <bool STORE_ALL>
__global__ void __launch_bounds__(LSTM_THREADS, 1)
lstm_kernel(const float* __restrict__ zpre,   // [B,T,G] (padded by G)
            const float* __restrict__ U,      // [H,G]
            float* __restrict__ h_all,        // [B,T,H] (layer 1)
            float* __restrict__ h_last)       // [B,H]   (layer 2)
{
    __shared__ __align__(16) float h_s[H * RPB];       // [k][r]
    __shared__ __align__(16) float z_s[4 * RPB * G];   // [q][r][logical c]

    const int tid = threadIdx.x;               // 0..799
    const int b0  = blockIdx.x * RPB;
    const int q   = tid / 200;                 // k-quarter (0..3)
    const int p   = tid % 200;                 // logical col pair
    const int o0  = (p & 1) * (2 * H) + (p >> 1); // original col of logical 2p
    const int row = tid / H;                   // gate row (tid<400)
    const int j   = tid % H;                   // gate hidden index

    // 25 U column-pairs (original cols o0, o0+H) for this (q, p)
    u64 U_pk[KQ];
#pragma unroll
    for (int m = 0; m < KQ; ++m) {
        const int k = q * KQ + m;
        U_pk[m] = f2pack(U[k * G + o0], U[k * G + o0 + H]);
    }

    for (int i = tid; i < H * RPB; i += LSTM_THREADS) h_s[i] = 0.f;

    float cs = 0.f, hv = 0.f;
    __syncthreads();

    const size_t bstride = (size_t)TT * G;
    // this thread prefetches zpre for batch row q at original cols o0, o0+H
    const float* zp = zpre + (size_t)(b0 + q) * bstride + o0;
    // running output pointer for layer-1 h store (avoids per-step mul chain)
    float* hop = STORE_ALL ? (h_all + (size_t)(b0 + row) * TT * H + j) : nullptr;

    float zr0 = zp[0], zr1 = zp[H];            // step-0 prefetch

    for (int t = 0; t < TT; ++t) {
        const u64 zpk = f2pack(zr0, zr1);
        u64 acc[RPB];
#pragma unroll
        for (int r = 0; r < RPB; ++r)          // STATIC indices only (no spill)
            acc[r] = (q == r) ? zpk : 0ull;

        // unconditional prefetch (array padded; final over-read unused)
        zp += G;
        zr0 = zp[0];
        zr1 = zp[H];

        const float4* hq4 = (const float4*)&h_s[q * KQ * RPB];
#pragma unroll
        for (int m = 0; m < KQ; ++m) {
            const float4 hq = hq4[m];          // rows 0..3 at k = q*KQ+m (broadcast)
            fma2(acc[0], f2dup(hq.x), U_pk[m]);
            fma2(acc[1], f2dup(hq.y), U_pk[m]);
            fma2(acc[2], f2dup(hq.z), U_pk[m]);
            fma2(acc[3], f2dup(hq.w), U_pk[m]);
        }

#pragma unroll
        for (int r = 0; r < RPB; ++r)
            *(u64*)&z_s[(q * RPB + r) * G + 2 * p] = acc[r];  // dense store
        __syncthreads();

        // gate phase: threads 0..399 own one (row, j)
        if (tid < RPB * H) {
            const ulonglong2 t0 = *(const ulonglong2*)&z_s[(0 * RPB + row) * G + 4 * j];
            const ulonglong2 t1 = *(const ulonglong2*)&z_s[(1 * RPB + row) * G + 4 * j];
            const ulonglong2 t2 = *(const ulonglong2*)&z_s[(2 * RPB + row) * G + 4 * j];
            const ulonglong2 t3 = *(const ulonglong2*)&z_s[(3 * RPB + row) * G + 4 * j];
            const u64 sa = add2(add2(t0.x, t1.x), add2(t2.x, t3.x)); // (zi, zf)
            const u64 sb = add2(add2(t0.y, t1.y), add2(t2.y, t3.y)); // (zg, zo)
            const float2 if_ = unpk(sa);
            const float2 go_ = unpk(sb);
            const float ig = fast_sig(if_.x);
            const float fg = fast_sig(if_.y);
            const float gg = fast_tanh(go_.x);
            const float og = fast_sig(go_.y);
            cs = fmaf(fg, cs, ig * gg);
            hv = og * fast_tanh(cs);
            h_s[j * RPB + row] = hv;
            if (STORE_ALL) {
                *hop = hv;
                hop += H;
            }
        }
        __syncthreads();
    }

    if (!STORE_ALL && tid < RPB * H)
        h_last[(b0 + row) * H + j] = hv;
}

// ---------------------------------------------------------------------------
// Final dense + sigmoid
// ---------------------------------------------------------------------------
__global__ void dense_kernel(const float* __restrict__ h_last,
                             const float* __restrict__ Wd,
                             const float* __restrict__ bd,
                             float* __restrict__ out)
{
    const int b = blockIdx.x * blockDim.x + threadIdx.x;
    if (b >= BATCH) return;
    float s = bd[0];
#pragma unroll
    for (int k = 0; k < H; ++k)
        s = fmaf(h_last[b * H + k], Wd[k], s);
    out[b] = 1.f / (1.f + __expf(-s));
}

// ---------------------------------------------------------------------------
extern "C" void kernel_launch(void* const* d_in, const int* in_sizes, int n_in,
                              void* d_out, int out_size)
{
    const float* x  = (const float*)d_in[0];
    const float* W1 = (const float*)d_in[1];
    const float* U1 = (const float*)d_in[2];
    const float* b1 = (const float*)d_in[3];
    const float* W2 = (const float*)d_in[4];
    const float* U2 = (const float*)d_in[5];
    const float* b2 = (const float*)d_in[6];
    const float* Wd = (const float*)d_in[7];
    const float* bd = (const float*)d_in[8];
    float* out = (float*)d_out;

    float *xw, *h1, *h2l;
    cudaGetSymbolAddress((void**)&xw,  g_xw);
    cudaGetSymbolAddress((void**)&h1,  g_h1);
    cudaGetSymbolAddress((void**)&h2l, g_h2last);

    // Layer 1
    pregemm_kernel<FF><<<NTOK / GEMM_ROWS, GEMM_THREADS>>>(x, W1, b1, xw);
    lstm_kernel<true><<<LSTM_CTAS, LSTM_THREADS>>>(xw, U1, h1, nullptr);
    // Layer 2
    pregemm_kernel<H><<<NTOK / GEMM_ROWS, GEMM_THREADS>>>(h1, W2, b2, xw);
    lstm_kernel<false><<<LSTM_CTAS, LSTM_THREADS>>>(xw, U2, nullptr, h2l);
    // Head
    dense_kernel<<<2, 256>>>(h2l, Wd, bd, out);
}

// round 17
// speedup vs baseline: 1.0390x; 1.0390x over previous
#include <cuda_runtime.h>
#include <math.h>
#include <stddef.h>

#define H 100
#define G 400            // 4*H
#define BATCH 512
#define TT 1024
#define FF 64
#define NTOK (BATCH * TT)        // 524288
#define RPB 4                    // batch rows per LSTM CTA
#define LSTM_CTAS (BATCH / RPB)  // 128
#define LSTM_THREADS 800         // (k-quarter, logical col-pair)
#define KQ 25                    // k per quarter
#define GEMM_ROWS 16
#define GEMM_THREADS 200
#define AS_STRIDE 24             // padded [k][row] stride (96B, 16B-aligned)

typedef unsigned long long u64;

// Scratch (static device allocation: no cudaMalloc allowed)
// g_xw padded by one timestep (G floats) so the lstm prefetch can over-read
// harmlessly on the final iteration (value unused).
__device__ float g_xw[(size_t)NTOK * G + G];   // 838.9 MB + pad
__device__ float g_h1[(size_t)NTOK * H];       // 209.7 MB
__device__ float g_h2last[BATCH * H];

// ---------------------------------------------------------------------------
// f32x2 packed helpers (sm_100+)
// ---------------------------------------------------------------------------
__device__ __forceinline__ u64 f2dup(float x)
{
    u64 r;
    asm("mov.b64 %0, {%1, %1};" : "=l"(r) : "f"(x));
    return r;
}
__device__ __forceinline__ u64 f2pack(float lo, float hi)
{
    u64 r;
    asm("mov.b64 %0, {%1, %2};" : "=l"(r) : "f"(lo), "f"(hi));
    return r;
}
__device__ __forceinline__ void fma2(u64& d, u64 a, u64 b)
{
    asm("fma.rn.f32x2 %0, %1, %2, %0;" : "+l"(d) : "l"(a), "l"(b));
}
__device__ __forceinline__ u64 add2(u64 a, u64 b)
{
    u64 r;
    asm("add.rn.f32x2 %0, %1, %2;" : "=l"(r) : "l"(a), "l"(b));
    return r;
}
__device__ __forceinline__ float2 unpk(u64 v)
{
    float2 r;
    asm("mov.b64 {%0, %1}, %2;" : "=f"(r.x), "=f"(r.y) : "l"(v));
    return r;
}

// ---------------------------------------------------------------------------
// Gate transcendentals via MUFU.TANH (sm_75+): 1 MUFU each, ~16cyc chain.
// sigma(x) = 0.5*tanh(x/2)+0.5. Op error ~1e-4; measured recurrence
// contraction (~200x, R2->R3 calibration) predicts final rel_err ~1e-6.
// ---------------------------------------------------------------------------
__device__ __forceinline__ float tanha(float x)
{
    float r;
    asm("tanh.approx.f32 %0, %1;" : "=f"(r) : "f"(x));
    return r;
}
__device__ __forceinline__ float fast_sig(float x)
{
    return fmaf(0.5f, tanha(0.5f * x), 0.5f);
}
__device__ __forceinline__ float fast_tanh(float x)
{
    return tanha(x);
}

// ---------------------------------------------------------------------------
// Pre-activation GEMM v3 (PROVEN 4784us version, unroll x1):
// out[N,400] = A[N,K] @ Wm[K,400] + bias. 200 threads = col-pairs, ROWS=16,
// acc lanes = row pairs, broadcast A quads, 4 CTAs/SM.
// ---------------------------------------------------------------------------
template <int K>
__global__ void __launch_bounds__(GEMM_THREADS, 4)
pregemm_kernel(const float* __restrict__ A, const float* __restrict__ Wm,
               const float* __restrict__ bias, float* __restrict__ out)
{
    __shared__ __align__(16) float A_s[K * AS_STRIDE];
    const int tid = threadIdx.x;
    const size_t row0 = (size_t)blockIdx.x * GEMM_ROWS;

    const float* Atile = A + row0 * K;
    for (int i = tid; i < GEMM_ROWS * K; i += GEMM_THREADS) {
        const int r = i / K;
        const int k = i % K;
        A_s[k * AS_STRIDE + r] = Atile[i];
    }
    __syncthreads();

    const int c0 = 2 * tid;                 // this thread's column pair
    u64 acc[16];                            // [4 quads][2 rowpairs][2 cols]
#pragma unroll
    for (int i = 0; i < 16; ++i) acc[i] = 0ull;

    float2 w = *(const float2*)&Wm[c0];     // k=0 prefetch
    for (int k = 0; k < K; ++k) {
        float2 wn;
        if (k + 1 < K) wn = *(const float2*)&Wm[(k + 1) * G + c0];
        const u64 w0 = f2dup(w.x);
        const u64 w1 = f2dup(w.y);
        const float* ak = &A_s[k * AS_STRIDE];
#pragma unroll
        for (int qd = 0; qd < 4; ++qd) {
            const ulonglong2 a = *(const ulonglong2*)(ak + qd * 4); // rows 4qd..4qd+3
            fma2(acc[qd * 4 + 0], a.x, w0);
            fma2(acc[qd * 4 + 1], a.x, w1);
            fma2(acc[qd * 4 + 2], a.y, w0);
            fma2(acc[qd * 4 + 3], a.y, w1);
        }
        if (k + 1 < K) w = wn;
    }

    const float2 bc = *(const float2*)&bias[c0];
#pragma unroll
    for (int qd = 0; qd < 4; ++qd) {
#pragma unroll
        for (int hp = 0; hp < 2; ++hp) {
            const float2 v0 = unpk(acc[qd * 4 + hp * 2 + 0]);
            const float2 v1 = unpk(acc[qd * 4 + hp * 2 + 1]);
            const int ra = 4 * qd + 2 * hp;
            *(float2*)&out[(row0 + ra) * G + c0]     = make_float2(v0.x + bc.x, v1.x + bc.y);
            *(float2*)&out[(row0 + ra + 1) * G + c0] = make_float2(v0.y + bc.x, v1.y + bc.y);
        }
    }
}

// ---------------------------------------------------------------------------
// Persistent LSTM layer: PROVEN structure (R16 base: unconditional prefetch,
// running h_all pointer). Only change vs R16: MUFU.TANH gates.
// ---------------------------------------------------------------------------
template <bool STORE_ALL>
__global__ void __launch_bounds__(LSTM_THREADS, 1)
lstm_kernel(const float* __restrict__ zpre,   // [B,T,G] (padded by G)
            const float* __restrict__ U,      // [H,G]
            float* __restrict__ h_all,        // [B,T,H] (layer 1)
            float* __restrict__ h_last)       // [B,H]   (layer 2)
{
    __shared__ __align__(16) float h_s[H * RPB];       // [k][r]
    __shared__ __align__(16) float z_s[4 * RPB * G];   // [q][r][logical c]

    const int tid = threadIdx.x;               // 0..799
    const int b0  = blockIdx.x * RPB;
    const int q   = tid / 200;                 // k-quarter (0..3)
    const int p   = tid % 200;                 // logical col pair
    const int o0  = (p & 1) * (2 * H) + (p >> 1); // original col of logical 2p
    const int row = tid / H;                   // gate row (tid<400)
    const int j   = tid % H;                   // gate hidden index

    // 25 U column-pairs (original cols o0, o0+H) for this (q, p)
    u64 U_pk[KQ];
#pragma unroll
    for (int m = 0; m < KQ; ++m) {
        const int k = q * KQ + m;
        U_pk[m] = f2pack(U[k * G + o0], U[k * G + o0 + H]);
    }

    for (int i = tid; i < H * RPB; i += LSTM_THREADS) h_s[i] = 0.f;

    float cs = 0.f, hv = 0.f;
    __syncthreads();

    const size_t bstride = (size_t)TT * G;
    // this thread prefetches zpre for batch row q at original cols o0, o0+H
    const float* zp = zpre + (size_t)(b0 + q) * bstride + o0;
    // running output pointer for layer-1 h store (avoids per-step mul chain)
    float* hop = STORE_ALL ? (h_all + (size_t)(b0 + row) * TT * H + j) : nullptr;

    float zr0 = zp[0], zr1 = zp[H];            // step-0 prefetch

    for (int t = 0; t < TT; ++t) {
        const u64 zpk = f2pack(zr0, zr1);
        u64 acc[RPB];
#pragma unroll
        for (int r = 0; r < RPB; ++r)          // STATIC indices only (no spill)
            acc[r] = (q == r) ? zpk : 0ull;

        // unconditional prefetch (array padded; final over-read unused)
        zp += G;
        zr0 = zp[0];
        zr1 = zp[H];

        const float4* hq4 = (const float4*)&h_s[q * KQ * RPB];
#pragma unroll
        for (int m = 0; m < KQ; ++m) {
            const float4 hq = hq4[m];          // rows 0..3 at k = q*KQ+m (broadcast)
            fma2(acc[0], f2dup(hq.x), U_pk[m]);
            fma2(acc[1], f2dup(hq.y), U_pk[m]);
            fma2(acc[2], f2dup(hq.z), U_pk[m]);
            fma2(acc[3], f2dup(hq.w), U_pk[m]);
        }

#pragma unroll
        for (int r = 0; r < RPB; ++r)
            *(u64*)&z_s[(q * RPB + r) * G + 2 * p] = acc[r];  // dense store
        __syncthreads();

        // gate phase: threads 0..399 own one (row, j)
        if (tid < RPB * H) {
            const ulonglong2 t0 = *(const ulonglong2*)&z_s[(0 * RPB + row) * G + 4 * j];
            const ulonglong2 t1 = *(const ulonglong2*)&z_s[(1 * RPB + row) * G + 4 * j];
            const ulonglong2 t2 = *(const ulonglong2*)&z_s[(2 * RPB + row) * G + 4 * j];
            const ulonglong2 t3 = *(const ulonglong2*)&z_s[(3 * RPB + row) * G + 4 * j];
            const u64 sa = add2(add2(t0.x, t1.x), add2(t2.x, t3.x)); // (zi, zf)
            const u64 sb = add2(add2(t0.y, t1.y), add2(t2.y, t3.y)); // (zg, zo)
            const float2 if_ = unpk(sa);
            const float2 go_ = unpk(sb);
            const float ig = fast_sig(if_.x);
            const float fg = fast_sig(if_.y);
            const float gg = fast_tanh(go_.x);
            const float og = fast_sig(go_.y);
            cs = fmaf(fg, cs, ig * gg);
            hv = og * fast_tanh(cs);
            h_s[j * RPB + row] = hv;
            if (STORE_ALL) {
                *hop = hv;
                hop += H;
            }
        }
        __syncthreads();
    }

    if (!STORE_ALL && tid < RPB * H)
        h_last[(b0 + row) * H + j] = hv;
}

// ---------------------------------------------------------------------------
// Final dense + sigmoid (exact fp32 path — negligible cost, keep precise)
// ---------------------------------------------------------------------------
__global__ void dense_kernel(const float* __restrict__ h_last,
                             const float* __restrict__ Wd,
                             const float* __restrict__ bd,
                             float* __restrict__ out)
{
    const int b = blockIdx.x * blockDim.x + threadIdx.x;
    if (b >= BATCH) return;
    float s = bd[0];
#pragma unroll
    for (int k = 0; k < H; ++k)
        s = fmaf(h_last[b * H + k], Wd[k], s);
    out[b] = 1.f / (1.f + __expf(-s));
}

// ---------------------------------------------------------------------------
extern "C" void kernel_launch(void* const* d_in, const int* in_sizes, int n_in,
                              void* d_out, int out_size)
{
    const float* x  = (const float*)d_in[0];
    const float* W1 = (const float*)d_in[1];
    const float* U1 = (const float*)d_in[2];
    const float* b1 = (const float*)d_in[3];
    const float* W2 = (const float*)d_in[4];
    const float* U2 = (const float*)d_in[5];
    const float* b2 = (const float*)d_in[6];
    const float* Wd = (const float*)d_in[7];
    const float* bd = (const float*)d_in[8];
    float* out = (float*)d_out;

    float *xw, *h1, *h2l;
    cudaGetSymbolAddress((void**)&xw,  g_xw);
    cudaGetSymbolAddress((void**)&h1,  g_h1);
    cudaGetSymbolAddress((void**)&h2l, g_h2last);

    // Layer 1
    pregemm_kernel<FF><<<NTOK / GEMM_ROWS, GEMM_THREADS>>>(x, W1, b1, xw);
    lstm_kernel<true><<<LSTM_CTAS, LSTM_THREADS>>>(xw, U1, h1, nullptr);
    // Layer 2
    pregemm_kernel<H><<<NTOK / GEMM_ROWS, GEMM_THREADS>>>(h1, W2, b2, xw);
    lstm_kernel<false><<<LSTM_CTAS, LSTM_THREADS>>>(xw, U2, nullptr, h2l);
    // Head
    dense_kernel<<<2, 256>>>(h2l, Wd, bd, out);
}